// round 6
// baseline (speedup 1.0000x reference)
#include <cuda_runtime.h>
#include <cstdint>
#include <cstddef>
#include <math.h>

// ---------------------------------------------------------------------------
// LSTM  I=256 H=512 O=10 B=64 T=2048  (fp32, f32x2 packed-FMA pipe)
// inputs: x[64,2048,256], W_ih[2048,256], W_hh[2048,512], b_ih[2048],
//         b_hh[2048], W_fc[10,512], b_fc[10]   -> out[64,10] f32
// ---------------------------------------------------------------------------

#define TSZ  2048
#define NCTA 128

typedef unsigned long long ull;

// scratch (__device__ globals are the sanctioned scratch mechanism)
__device__ float    g_xg[268435456];     // 1 GiB: [T][4H][B]  (2048*2048*64)
__device__ float    g_h[2 * 512 * 64];   // double-buffered h: [H][B]
__device__ float    g_bias[2048];        // b_ih + b_hh
__device__ unsigned g_count;             // chip-barrier counter

// ---- packed f32x2 helpers (Blackwell dual-fp32 pipe) ----------------------
__device__ __forceinline__ ull pk2(float a, float b) {
    ull r; asm("mov.b64 %0,{%1,%2};" : "=l"(r) : "f"(a), "f"(b)); return r;
}
__device__ __forceinline__ ull splat2(float a) {
    ull r; asm("mov.b64 %0,{%1,%1};" : "=l"(r) : "f"(a)); return r;
}
__device__ __forceinline__ void upk2(ull v, float& a, float& b) {
    asm("mov.b64 {%0,%1},%2;" : "=f"(a), "=f"(b) : "l"(v));
}
__device__ __forceinline__ ull fma2(ull a, ull b, ull c) {
    ull d; asm("fma.rn.f32x2 %0,%1,%2,%3;" : "=l"(d) : "l"(a), "l"(b), "l"(c));
    return d;
}

// ---------------------------------------------------------------------------
__global__ void k_init(const float* __restrict__ bih, const float* __restrict__ bhh) {
    int tid = blockIdx.x * blockDim.x + threadIdx.x;
    int nt  = gridDim.x * blockDim.x;
    if (tid < 2048) g_bias[tid] = bih[tid] + bhh[tid];
    for (int i = tid; i < 2 * 512 * 64; i += nt) g_h[i] = 0.0f;
    if (tid == 0) g_count = 0u;
}

// ---------------------------------------------------------------------------
// Phase 1: xg[t][row][b] = sum_i W_ih[row][i] * x[b][t][i] + bias[row]
// grid (16 row-tiles, 2048 t), 256 threads. Tile 128x64, K-chunks of 16,
// thread tile 8 rows x 4 cols (2 f32x2 col-pairs).
// ---------------------------------------------------------------------------
__global__ void __launch_bounds__(256) k_inproj(const float* __restrict__ x,
                                                const float* __restrict__ Wih) {
    __shared__ __align__(16) float As[16 * 132];  // [k][row], pad 132
    __shared__ __align__(16) float Bs[16 * 66];   // [k][b],   pad 66 (8B-aligned rows)

    const int tid = threadIdx.x;
    const int bx  = blockIdx.x;    // row tile 0..15
    const int t   = blockIdx.y;    // 0..2047
    const int tr  = tid >> 4, tc = tid & 15;
    const int r0  = tr * 8,  c0 = tc * 4;
    const int kkg = tid & 3;       // k-subgroup for staging
    const int bb  = tid >> 2;      // 0..63

    ull acc[8][2];
#pragma unroll
    for (int i = 0; i < 8; i++) { acc[i][0] = 0ull; acc[i][1] = 0ull; }

    for (int k0 = 0; k0 < 256; k0 += 16) {
        // stage A (coalesced along k, conflict-light STS)
#pragma unroll
        for (int j = 0; j < 2; j++) {
            int rr = (tid >> 2) + j * 64;
            float4 av = *(const float4*)(Wih + (size_t)(bx * 128 + rr) * 256 + k0 + kkg * 4);
            As[(kkg * 4 + 0) * 132 + rr] = av.x;
            As[(kkg * 4 + 1) * 132 + rr] = av.y;
            As[(kkg * 4 + 2) * 132 + rr] = av.z;
            As[(kkg * 4 + 3) * 132 + rr] = av.w;
        }
        // stage B: Bs[k][b] = x[b][t][k0+k]
        {
            float4 bv = *(const float4*)(x + ((size_t)bb * 2048 + t) * 256 + k0 + kkg * 4);
            Bs[(kkg * 4 + 0) * 66 + bb] = bv.x;
            Bs[(kkg * 4 + 1) * 66 + bb] = bv.y;
            Bs[(kkg * 4 + 2) * 66 + bb] = bv.z;
            Bs[(kkg * 4 + 3) * 66 + bb] = bv.w;
        }
        __syncthreads();
#pragma unroll
        for (int k = 0; k < 16; k++) {
            float4 a0 = *(const float4*)&As[k * 132 + r0];
            float4 a1 = *(const float4*)&As[k * 132 + r0 + 4];
            ull b0 = *(const ull*)&Bs[k * 66 + c0];
            ull b1 = *(const ull*)&Bs[k * 66 + c0 + 2];
            ull sp;
            sp = splat2(a0.x); acc[0][0] = fma2(sp, b0, acc[0][0]); acc[0][1] = fma2(sp, b1, acc[0][1]);
            sp = splat2(a0.y); acc[1][0] = fma2(sp, b0, acc[1][0]); acc[1][1] = fma2(sp, b1, acc[1][1]);
            sp = splat2(a0.z); acc[2][0] = fma2(sp, b0, acc[2][0]); acc[2][1] = fma2(sp, b1, acc[2][1]);
            sp = splat2(a0.w); acc[3][0] = fma2(sp, b0, acc[3][0]); acc[3][1] = fma2(sp, b1, acc[3][1]);
            sp = splat2(a1.x); acc[4][0] = fma2(sp, b0, acc[4][0]); acc[4][1] = fma2(sp, b1, acc[4][1]);
            sp = splat2(a1.y); acc[5][0] = fma2(sp, b0, acc[5][0]); acc[5][1] = fma2(sp, b1, acc[5][1]);
            sp = splat2(a1.z); acc[6][0] = fma2(sp, b0, acc[6][0]); acc[6][1] = fma2(sp, b1, acc[6][1]);
            sp = splat2(a1.w); acc[7][0] = fma2(sp, b0, acc[7][0]); acc[7][1] = fma2(sp, b1, acc[7][1]);
        }
        __syncthreads();
    }
#pragma unroll
    for (int i = 0; i < 8; i++) {
        int row = bx * 128 + r0 + i;
        float bias = g_bias[row];
        float p0, p1, p2, p3;
        upk2(acc[i][0], p0, p1);
        upk2(acc[i][1], p2, p3);
        *(float4*)(g_xg + ((size_t)t * 2048 + row) * 64 + c0) =
            make_float4(p0 + bias, p1 + bias, p2 + bias, p3 + bias);
    }
}

// ---------------------------------------------------------------------------
// Phase 2: persistent recurrence. 128 CTAs x 256 thr. CTA owns hidden units
// h0..h0+3 -> 16 gate rows (rloc = u*4+g). W slab in smem for all steps.
// Per step: stage h in 2x16KB smem chunks (ldcg), f32x2 GEMM, gates via smem,
// activations, write h_next, chip barrier (release-count / acquire-spin).
// ---------------------------------------------------------------------------
__global__ void __launch_bounds__(256, 1) k_rec(const float* __restrict__ Whh) {
    extern __shared__ __align__(16) float sm[];
    float* Wsh = sm;                   // 16 * 520
    float* hsh = sm + 16 * 520;        // 2 * 4096
    float* gsh = sm + 16 * 520 + 8192; // 16 * 64

    const int tid = threadIdx.x;
    const int h0  = blockIdx.x * 4;
    const int rloc = tid >> 4, cg = tid & 15, c0 = cg * 4;
    const int u = rloc >> 2, g = rloc & 3;
    const int grow = g * 512 + h0 + u;   // global gate row of this thread

    // load W_hh slab: row rloc <- Whh[(rloc&3)*512 + h0 + (rloc>>2)]
#pragma unroll
    for (int j = 0; j < 8; j++) {
        int flat = tid + j * 256;          // float4 idx 0..2047
        int row = flat >> 7, c4 = flat & 127;
        int ru = row >> 2, rg = row & 3;
        float4 wv = *(const float4*)(Whh + (size_t)(rg * 512 + h0 + ru) * 512 + c4 * 4);
        *(float4*)&Wsh[row * 520 + c4 * 4] = wv;
    }
    float cstate = 0.0f;                   // this thread's cell (u2 = tid>>6, b = tid&63)
    __syncthreads();

    for (int s = 0; s < TSZ; s++) {
        const float* hin  = g_h + (s & 1) * 32768;
        float*       hout = g_h + ((s + 1) & 1) * 32768;

        const float4* xp = (const float4*)(g_xg + ((size_t)s * 2048 + grow) * 64 + c0);
        float4 xg4 = __ldcs(xp);
        ull acc0 = pk2(xg4.x, xg4.y);
        ull acc1 = pk2(xg4.z, xg4.w);

        // stage chunk 0 (L1-bypass: peer CTAs wrote this buffer last step)
        {
            const float4* src = (const float4*)hin;
            float4* dst = (float4*)hsh;
            dst[tid]       = __ldcg(src + tid);
            dst[tid + 256] = __ldcg(src + tid + 256);
            dst[tid + 512] = __ldcg(src + tid + 512);
            dst[tid + 768] = __ldcg(src + tid + 768);
        }
        __syncthreads();

        for (int kc = 0; kc < 8; kc++) {
            float4 v0, v1, v2, v3;
            if (kc < 7) {  // prefetch next chunk into regs; latency hidden by compute
                const float4* src = (const float4*)(hin + (kc + 1) * 4096);
                v0 = __ldcg(src + tid);       v1 = __ldcg(src + tid + 256);
                v2 = __ldcg(src + tid + 512); v3 = __ldcg(src + tid + 768);
            }
            const float* hb = hsh + (kc & 1) * 4096;
            const float* wr = Wsh + rloc * 520 + kc * 64;
#pragma unroll
            for (int k = 0; k < 64; k += 4) {
                float4 a4 = *(const float4*)(wr + k);
                const float* hp = hb + k * 64 + c0;
                acc0 = fma2(splat2(a4.x), *(const ull*)(hp),       acc0);
                acc1 = fma2(splat2(a4.x), *(const ull*)(hp + 2),   acc1);
                acc0 = fma2(splat2(a4.y), *(const ull*)(hp + 64),  acc0);
                acc1 = fma2(splat2(a4.y), *(const ull*)(hp + 66),  acc1);
                acc0 = fma2(splat2(a4.z), *(const ull*)(hp + 128), acc0);
                acc1 = fma2(splat2(a4.z), *(const ull*)(hp + 130), acc1);
                acc0 = fma2(splat2(a4.w), *(const ull*)(hp + 192), acc0);
                acc1 = fma2(splat2(a4.w), *(const ull*)(hp + 194), acc1);
            }
            if (kc < 7) {
                float4* dst = (float4*)(hsh + ((kc + 1) & 1) * 4096);
                dst[tid] = v0; dst[tid + 256] = v1; dst[tid + 512] = v2; dst[tid + 768] = v3;
            }
            __syncthreads();
        }

        // publish raw gate pre-activations to smem
        {
            float p0, p1, p2, p3;
            upk2(acc0, p0, p1);
            upk2(acc1, p2, p3);
            *(float4*)&gsh[rloc * 64 + c0] = make_float4(p0, p1, p2, p3);
        }
        __syncthreads();

        // cell update: one cell per thread (u2, b); gate row rloc' = u2*4 + gate
        {
            int u2 = tid >> 6, b = tid & 63;
            float ig = gsh[(u2 * 4 + 0) * 64 + b];
            float fg = gsh[(u2 * 4 + 1) * 64 + b];
            float gg = gsh[(u2 * 4 + 2) * 64 + b];
            float og = gsh[(u2 * 4 + 3) * 64 + b];
            ig = 1.0f / (1.0f + expf(-ig));
            fg = 1.0f / (1.0f + expf(-fg));
            gg = tanhf(gg);
            og = 1.0f / (1.0f + expf(-og));
            cstate = fg * cstate + ig * gg;
            hout[(h0 + u2) * 64 + b] = og * tanhf(cstate);
        }
        __syncthreads();   // all hout STGs done before release

        // chip-wide barrier (monotonic counter; reset by k_init per launch)
        if (tid == 0) {
            __threadfence();                       // release (gpu scope, cumulative)
            atomicAdd(&g_count, 1u);
            unsigned target = (unsigned)(s + 1) * NCTA;
            while (*(volatile unsigned*)&g_count < target) { }
            __threadfence();                       // acquire
        }
        __syncthreads();
    }
}

// ---------------------------------------------------------------------------
// FC head: out[b][o] = sum_h h_last[h][b] * W_fc[o][h] + b_fc[o]
// h_last = g_h buffer 0 (written at step 2047). grid 10 x 64 threads.
// ---------------------------------------------------------------------------
__global__ void k_fc(const float* __restrict__ Wfc, const float* __restrict__ bfc,
                     float* __restrict__ out) {
    int o = blockIdx.x;
    int b = threadIdx.x;
    const float* w = Wfc + o * 512;
    float a0 = 0.f, a1 = 0.f, a2 = 0.f, a3 = 0.f;
#pragma unroll 4
    for (int k = 0; k < 512; k += 4) {
        a0 += g_h[(k + 0) * 64 + b] * w[k + 0];
        a1 += g_h[(k + 1) * 64 + b] * w[k + 1];
        a2 += g_h[(k + 2) * 64 + b] * w[k + 2];
        a3 += g_h[(k + 3) * 64 + b] * w[k + 3];
    }
    out[b * 10 + o] = a0 + a1 + a2 + a3 + bfc[o];
}

// ---------------------------------------------------------------------------
extern "C" void kernel_launch(void* const* d_in, const int* in_sizes, int n_in,
                              void* d_out, int out_size) {
    const float* x    = (const float*)d_in[0];
    const float* W_ih = (const float*)d_in[1];
    const float* W_hh = (const float*)d_in[2];
    const float* b_ih = (const float*)d_in[3];
    const float* b_hh = (const float*)d_in[4];
    const float* W_fc = (const float*)d_in[5];
    const float* b_fc = (const float*)d_in[6];
    float* out = (float*)d_out;

    const int SMEM_REC = (16 * 520 + 2 * 4096 + 16 * 64) * 4;  // 70144 B
    cudaFuncSetAttribute(k_rec, cudaFuncAttributeMaxDynamicSharedMemorySize, SMEM_REC);

    k_init<<<64, 256>>>(b_ih, b_hh);
    k_inproj<<<dim3(16, 2048), 256>>>(x, W_ih);
    k_rec<<<NCTA, 256, SMEM_REC>>>(W_hh);
    k_fc<<<10, 64>>>(W_fc, b_fc, out);
}